// round 13
// baseline (speedup 1.0000x reference)
#include <cuda_runtime.h>
#include <cstdint>

#define OC 64
#define IC 208
#define EPSV 1e-5f
#define KTAPS 352
#define NK16 22
#define CHUNK_U4 256
#define BCH_U4 (NK16 * CHUNK_U4)
#define PCH 57760                       // 2*20*38*38 per channel (deinterleaved layout)
#define INWORDS 4536                    // 2 par * 12 w * 189 rows

__device__ float g_P[(size_t)4 * IC * PCH];    // [b][c][par][pw2 20][pd 38][ph 38]
__device__ uint4 g_W[(size_t)IC * BCH_U4];     // [c][q][nblk][lane] = {b0h,b1h,b0l,b1l}
__device__ float g_ss[OC];
__device__ float g_scale[OC];

// ---------------- helpers ----------------
static __device__ __forceinline__ uint32_t pack_bf16x2(float hi, float lo) {
    uint32_t r; asm("cvt.rn.bf16x2.f32 %0, %1, %2;" : "=r"(r) : "f"(hi), "f"(lo));
    return r;
}
static __device__ __forceinline__ void unpack_bf16x2(uint32_t p, float& lo, float& hi) {
    lo = __uint_as_float(p << 16);
    hi = __uint_as_float(p & 0xffff0000u);
}
static __device__ __forceinline__ void mma_bf16(float* d, const uint32_t* a,
                                                uint32_t b0, uint32_t b1) {
    asm volatile("mma.sync.aligned.m16n8k16.row.col.f32.bf16.bf16.f32 "
        "{%0,%1,%2,%3}, {%4,%5,%6,%7}, {%8,%9}, {%0,%1,%2,%3};"
        : "+f"(d[0]), "+f"(d[1]), "+f"(d[2]), "+f"(d[3])
        : "r"(a[0]), "r"(a[1]), "r"(a[2]), "r"(a[3]), "r"(b0), "r"(b1));
}

#define CPA(dst, src)  asm volatile("cp.async.cg.shared.global [%0], [%1], 16;" :: "r"(dst), "l"(src))
#define CPA4(dst, src) asm volatile("cp.async.ca.shared.global [%0], [%1], 4;"  :: "r"(dst), "l"(src))
#define CPC() asm volatile("cp.async.commit_group;" ::)
#define CPW1() asm volatile("cp.async.wait_group 1;" ::: "memory")
#define CPW0() asm volatile("cp.async.wait_group 0;" ::: "memory")

// ---------------- K1: build weights into mma B-fragment layout ----------------
__global__ void build_w_kernel(
    int c0, int c1,
    const float* __restrict__ wss, const float* __restrict__ wsv, const float* __restrict__ wst,
    const float* __restrict__ wvs, const float* __restrict__ wvv, const float* __restrict__ wvt,
    const float* __restrict__ bss, const float* __restrict__ bsv, const float* __restrict__ bst,
    const float* __restrict__ bvs, const float* __restrict__ bvv, const float* __restrict__ bvt) {
    int idx = blockIdx.x * blockDim.x + threadIdx.x;
    int n = (c1 - c0) * KTAPS * 64;
    if (idx >= n) return;
    int oc  = idx & 63;
    int tap = (idx >> 6) % KTAPS;
    int c   = c0 + idx / (KTAPS * 64);

    float val = 0.f;
    if (tap < 343) {
        int u, io, dout;
        if (oc < 16) { u = oc; io = 0; dout = 1; }
        else         { u = (oc - 16) / 3; io = (oc - 16) % 3; dout = 3; }
        int v, ji, din;
        if (c < 16)       { v = c;            ji = 0;            din = 1; }
        else if (c < 64)  { v = (c - 16) / 3; ji = (c - 16) % 3; din = 3; }
        else              { v = (c - 64) / 9; ji = (c - 64) % 9; din = 9; }
        const float* w; const float* bs; int nb;
        if (oc < 16) {
            if (c < 16)      { w = wss; bs = bss; nb = 3; }
            else if (c < 64) { w = wsv; bs = bsv; nb = 3; }
            else             { w = wst; bs = bst; nb = 9; }
        } else {
            if (c < 16)      { w = wvs; bs = bvs; nb = 3; }
            else if (c < 64) { w = wvv; bs = bvv; nb = 9; }
            else             { w = wvt; bs = bvt; nb = 21; }
        }
        for (int bb = 0; bb < nb; bb++)
            val = fmaf(w[(u * 16 + v) * nb + bb],
                       bs[((bb * dout + io) * din + ji) * 343 + tap], val);
    }
    uint32_t hp = pack_bf16x2(0.f, val);
    float hf = __uint_as_float(hp << 16);
    uint32_t lp = pack_bf16x2(0.f, val - hf);
    uint16_t hb = (uint16_t)(hp & 0xffff);
    uint16_t lb = (uint16_t)(lp & 0xffff);

    int q = tap >> 4, kk = tap & 15;
    int j = oc >> 3;
    int lane = ((oc & 7) << 2) + ((kk & 7) >> 1);
    size_t u4 = ((size_t)c * NK16 + q) * CHUNK_U4 + j * 32 + lane;
    uint16_t* h16 = (uint16_t*)&g_W[u4];
    int word = kk >> 3, half = kk & 1;
    h16[word * 2 + half]     = hb;
    h16[4 + word * 2 + half] = lb;
}

// ---------------- K2: padded svt, w-parity deinterleaved + transposed ----------------
__global__ void pad_kernel(const float* __restrict__ sv) {
    long long idx = (long long)blockIdx.x * 256 + threadIdx.x;
    if (idx >= (long long)4 * IC * PCH) return;
    int bc = (int)(idx / PCH);
    int r  = (int)(idx - (long long)bc * PCH);
    int b = bc / IC, c = bc % IC;
    int ph  = r % 38;  r /= 38;
    int pd  = r % 38;  r /= 38;
    int pw2 = r % 20;
    int par = r / 20;
    int id = pd - 3, ih = ph - 3, iw = 2 * pw2 + par - 3;
    float val = 0.f;
    if ((unsigned)id < 32u && (unsigned)ih < 32u && (unsigned)iw < 32u) {
        int off = id * 1024 + ih * 32 + iw;
        const float* svb = sv + (size_t)b * 64 * 32768;
        if (c < 64) val = svb[(size_t)c * 32768 + off];
        else {
            int cc = c - 64, u = cc / 9, comp = cc % 9;
            val = svb[(size_t)(16 + u * 3 + comp / 3) * 32768 + off] *
                  svb[(size_t)(16 + u * 3 + comp % 3) * 32768 + off];
        }
    }
    g_P[idx] = val;
}

// gather 16 A values for one q given base pointer and tap offsets
#define LOAD_F(dst, p0, o0, o1, o2, o3) do {                                   \
    (dst)[0] = (p0)[(o0)];     (dst)[1] = (p0)[(o1)];                          \
    (dst)[2] = (p0)[2 + (o0)]; (dst)[3] = (p0)[2 + (o1)];                      \
    (dst)[4] = (p0)[(o2)];     (dst)[5] = (p0)[(o3)];                          \
    (dst)[6] = (p0)[2 + (o2)]; (dst)[7] = (p0)[2 + (o3)];                      \
    (dst)[8] = (p0)[4 + (o0)]; (dst)[9] = (p0)[4 + (o1)];                      \
    (dst)[10] = (p0)[6 + (o0)]; (dst)[11] = (p0)[6 + (o1)];                    \
    (dst)[12] = (p0)[4 + (o2)]; (dst)[13] = (p0)[4 + (o3)];                    \
    (dst)[14] = (p0)[6 + (o2)]; (dst)[15] = (p0)[6 + (o3)];                    \
} while (0)

// ---------------- K3: mma.sync bf16x3, M-pair warps + K-split, q-pipelined ----------------
extern __shared__ float smem[];

__global__ void __launch_bounds__(256, 1)
conv_kernel(float* __restrict__ out) {
    int*   tapoff = (int*)smem;
    float* s_in   = smem + 352;
    uint4* s_B    = (uint4*)(smem + 352 + 2 * INWORDS);
    float* s_red  = (float*)s_B;

    const int tid = threadIdx.x, lane = tid & 31, w = tid >> 5;
    const int mg = w & 3, khf = w >> 2;
    const int tile = blockIdx.x, b = blockIdx.y;
    const int td = (tile >> 2) * 2, th = ((tile >> 1) & 1) * 8, tw = (tile & 1) * 8;

    for (int t = tid; t < KTAPS; t += 256) {
        int o = 0;
        if (t < 343) {
            int kd = t / 49, r = t % 49, kh = r / 7, kw = r % 7;
            o = (kw & 1) * 2268 + (kw >> 1) * 189 + kd * 21 + kh;
        }
        tapoff[t] = o;
    }

    const int c4 = lane & 3;
    const int r8 = lane >> 2;
    const int gbase = r8 * 189 + (mg >> 1) * 42 + (mg & 1) * 8;

    const uint32_t inb = (uint32_t)__cvta_generic_to_shared(s_in);
    const uint32_t Bb  = (uint32_t)__cvta_generic_to_shared(s_B);

    auto stage = [&](int c) {
        int buf = c & 1;
        const float* chb = g_P + ((size_t)b * IC + c) * PCH;
        uint32_t dsti = inb + (uint32_t)buf * INWORDS * 4;
        for (int i = tid; i < INWORDS; i += 256) {
            int rem = i;
            int par = rem / 2268;  rem -= par * 2268;
            int w12 = rem / 189;   rem -= w12 * 189;
            int dd  = rem / 21;
            int hh  = rem - dd * 21;
            const float* src = chb + (size_t)(((par * 20 + tw + w12) * 38 + (2 * td + dd)) * 38
                                              + 2 * th + hh);
            CPA4(dsti + i * 4, src);
        }
        const uint4* bsrc = g_W + (size_t)c * BCH_U4;
        uint32_t dstb = Bb + (uint32_t)buf * BCH_U4 * 16;
        for (int i = tid; i < BCH_U4; i += 256) CPA(dstb + i * 16, bsrc + i);
    };

    float acc0[8][4], acc1[8][4];
#pragma unroll
    for (int j = 0; j < 8; j++)
#pragma unroll
        for (int k = 0; k < 4; k++) { acc0[j][k] = 0.f; acc1[j][k] = 0.f; }

    stage(0); CPC();
    stage(1); CPC();

    const int q0 = khf * 11;
    const int* tq0 = tapoff + q0 * 16 + 2 * c4;

    for (int c = 0; c < IC; c++) {
        if (c < IC - 1) CPW1(); else CPW0();
        __syncthreads();

        const float* si = s_in + (c & 1) * INWORDS;
        const uint4* Bc = s_B + (c & 1) * BCH_U4;
        const float* p0 = si + gbase;

        // prologue: gather q0
        int o0 = tq0[0], o1 = tq0[1], o2 = tq0[8], o3 = tq0[9];
        float fv[16];
        LOAD_F(fv, p0, o0, o1, o2, o3);

#pragma unroll 1
        for (int ql = 0; ql < 11; ql++) {
            // prefetch next q's A values (overlaps with this q's MMAs)
            float nv[16];
            if (ql < 10) {
                const int* tqn = tapoff + (q0 + ql + 1) * 16 + 2 * c4;
                int n0 = tqn[0], n1 = tqn[1], n2 = tqn[8], n3 = tqn[9];
                LOAD_F(nv, p0, n0, n1, n2, n3);
            }

            uint32_t ah[8], al[8];
            ah[0] = pack_bf16x2(fv[1], fv[0]);  ah[1] = pack_bf16x2(fv[3], fv[2]);
            ah[2] = pack_bf16x2(fv[5], fv[4]);  ah[3] = pack_bf16x2(fv[7], fv[6]);
            ah[4] = pack_bf16x2(fv[9], fv[8]);  ah[5] = pack_bf16x2(fv[11], fv[10]);
            ah[6] = pack_bf16x2(fv[13], fv[12]); ah[7] = pack_bf16x2(fv[15], fv[14]);
            float hl, hh;
            unpack_bf16x2(ah[0], hl, hh); al[0] = pack_bf16x2(fv[1] - hh, fv[0] - hl);
            unpack_bf16x2(ah[1], hl, hh); al[1] = pack_bf16x2(fv[3] - hh, fv[2] - hl);
            unpack_bf16x2(ah[2], hl, hh); al[2] = pack_bf16x2(fv[5] - hh, fv[4] - hl);
            unpack_bf16x2(ah[3], hl, hh); al[3] = pack_bf16x2(fv[7] - hh, fv[6] - hl);
            unpack_bf16x2(ah[4], hl, hh); al[4] = pack_bf16x2(fv[9] - hh, fv[8] - hl);
            unpack_bf16x2(ah[5], hl, hh); al[5] = pack_bf16x2(fv[11] - hh, fv[10] - hl);
            unpack_bf16x2(ah[6], hl, hh); al[6] = pack_bf16x2(fv[13] - hh, fv[12] - hl);
            unpack_bf16x2(ah[7], hl, hh); al[7] = pack_bf16x2(fv[15] - hh, fv[14] - hl);

            const uint4* Bq = Bc + (q0 + ql) * CHUNK_U4 + lane;
#pragma unroll
            for (int j = 0; j < 8; j++) {
                uint4 bb = Bq[j * 32];
                mma_bf16(acc0[j], ah,     bb.x, bb.y);
                mma_bf16(acc0[j], al,     bb.x, bb.y);
                mma_bf16(acc0[j], ah,     bb.z, bb.w);
                mma_bf16(acc1[j], ah + 4, bb.x, bb.y);
                mma_bf16(acc1[j], al + 4, bb.x, bb.y);
                mma_bf16(acc1[j], ah + 4, bb.z, bb.w);
            }

            if (ql < 10) {
#pragma unroll
                for (int k = 0; k < 16; k++) fv[k] = nv[k];
            }
        }

        if (c + 2 < IC) {
            __syncthreads();
            stage(c + 2); CPC();
        }
    }

    // ---- K-half reduction ----
    __syncthreads();
    if (khf == 1) {
        float* dst = s_red + (size_t)(mg * 32 + lane) * 64;
#pragma unroll
        for (int j = 0; j < 8; j++)
#pragma unroll
            for (int k = 0; k < 4; k++) {
                dst[j * 4 + k]      = acc0[j][k];
                dst[32 + j * 4 + k] = acc1[j][k];
            }
    }
    __syncthreads();
    if (khf == 0) {
        const float* src = s_red + (size_t)(mg * 32 + lane) * 64;
#pragma unroll
        for (int j = 0; j < 8; j++)
#pragma unroll
            for (int k = 0; k < 4; k++) {
                acc0[j][k] += src[j * 4 + k];
                acc1[j][k] += src[32 + j * 4 + k];
            }

        float* ob = out + (size_t)b * OC * 4096;
        int vv[4];
#pragma unroll
        for (int s = 0; s < 4; s++) {
            int m = mg * 32 + s * 8 + r8;
            vv[s] = (td + (m >> 6)) * 256 + (th + ((m >> 3) & 7)) * 16 + (tw + (m & 7));
        }
#pragma unroll
        for (int j = 0; j < 8; j++) {
            int oc0 = j * 8 + 2 * c4;
            ob[(size_t)oc0 * 4096 + vv[0]]       = acc0[j][0];
            ob[(size_t)(oc0 + 1) * 4096 + vv[0]] = acc0[j][1];
            ob[(size_t)oc0 * 4096 + vv[1]]       = acc0[j][2];
            ob[(size_t)(oc0 + 1) * 4096 + vv[1]] = acc0[j][3];
            ob[(size_t)oc0 * 4096 + vv[2]]       = acc1[j][0];
            ob[(size_t)(oc0 + 1) * 4096 + vv[2]] = acc1[j][1];
            ob[(size_t)oc0 * 4096 + vv[3]]       = acc1[j][2];
            ob[(size_t)(oc0 + 1) * 4096 + vv[3]] = acc1[j][3];
        }
    }
}

// ---------------- epilogue kernels ----------------
__global__ void sumsq_kernel(const float* __restrict__ y) {
    __shared__ float red[256];
    const int ch = blockIdx.x, tid = threadIdx.x;
    float s = 0.f;
    for (int i = tid; i < 4 * 4096; i += 256) {
        int b = i >> 12, sp = i & 4095;
        float v = y[((size_t)b * OC + ch) * 4096 + sp];
        s = fmaf(v, v, s);
    }
    red[tid] = s;
    __syncthreads();
    for (int o = 128; o > 0; o >>= 1) {
        if (tid < o) red[tid] += red[tid + o];
        __syncthreads();
    }
    if (tid == 0) g_ss[ch] = red[0];
}

__global__ void finalize_kernel(const float* __restrict__ bngs, const float* __restrict__ bngv) {
    int ch = threadIdx.x;
    float sc;
    if (ch < 16) sc = bngs[ch] / sqrtf(g_ss[ch] / 16384.f + EPSV);
    else {
        int u = (ch - 16) / 3;
        sc = bngv[u] / sqrtf((g_ss[16 + 3 * u] + g_ss[17 + 3 * u] + g_ss[18 + 3 * u]) / 49152.f + EPSV);
    }
    g_scale[ch] = sc;
}

__global__ void scale_act_kernel(float* __restrict__ y, const float* __restrict__ bias) {
    int i = blockIdx.x * 256 + threadIdx.x;
    int ch = (i >> 12) & 63;
    float v = y[i] * g_scale[ch];
    if (ch < 16) v = fmaxf(v + bias[ch], 0.f);
    y[i] = v;
}

// ---------------- launch ----------------
extern "C" void kernel_launch(void* const* d_in, const int* in_sizes, int n_in,
                              void* d_out, int out_size) {
    const float* sv = (const float*)d_in[0];
    const float *wss, *wsv, *wst, *wvs, *wvv, *wvt;
    const float *bss, *bsv, *bst, *bvs, *bvv, *bvt;
    if (in_sizes[1] == 1029) {
        bss = (const float*)d_in[1];  wss = (const float*)d_in[2];
        bsv = (const float*)d_in[3];  wsv = (const float*)d_in[4];
        bst = (const float*)d_in[5];  wst = (const float*)d_in[6];
        bvs = (const float*)d_in[7];  wvs = (const float*)d_in[8];
        bvv = (const float*)d_in[9];  wvv = (const float*)d_in[10];
        bvt = (const float*)d_in[11]; wvt = (const float*)d_in[12];
    } else {
        wss = (const float*)d_in[1];  wsv = (const float*)d_in[2];  wst = (const float*)d_in[3];
        wvs = (const float*)d_in[4];  wvv = (const float*)d_in[5];  wvt = (const float*)d_in[6];
        bss = (const float*)d_in[7];  bsv = (const float*)d_in[8];  bst = (const float*)d_in[9];
        bvs = (const float*)d_in[10]; bvv = (const float*)d_in[11]; bvt = (const float*)d_in[12];
    }
    const float* bngs = (const float*)d_in[13];
    const float* bngv = (const float*)d_in[14];
    const float* bias = (const float*)d_in[15];
    float* out = (float*)d_out;

    const int SMEM_BYTES = (352 + 2 * INWORDS + 2 * BCH_U4 * 4) * 4;   // 217,920 B
    cudaFuncSetAttribute(conv_kernel, cudaFuncAttributeMaxDynamicSharedMemorySize, SMEM_BYTES);

    int n1 = 104 * KTAPS * 64;
    build_w_kernel<<<(n1 + 255) / 256, 256>>>(0, 104, wss, wsv, wst, wvs, wvv, wvt,
                                              bss, bsv, bst, bvs, bvv, bvt);
    build_w_kernel<<<(n1 + 255) / 256, 256>>>(104, 208, wss, wsv, wst, wvs, wvv, wvt,
                                              bss, bsv, bst, bvs, bvv, bvt);
    long long nP = (long long)4 * IC * PCH;
    pad_kernel<<<(unsigned)((nP + 255) / 256), 256>>>(sv);
    conv_kernel<<<dim3(32, 4), 256, SMEM_BYTES>>>(out);
    sumsq_kernel<<<64, 256>>>(out);
    finalize_kernel<<<1, 64>>>(bngs, bngv);
    scale_act_kernel<<<4096, 256>>>(out, bias);
}

// round 14
// speedup vs baseline: 1.2977x; 1.2977x over previous
#include <cuda_runtime.h>
#include <cstdint>

#define OC 64
#define IC 208
#define EPSV 1e-5f
#define PD 38
#define PH 38
#define PW 40
#define PCH (PD * PH * PW)
#define KTAPS 352
#define NK16 22                       // k16 steps per channel
#define CHUNK_U4 256                  // uint4 per k16 B-chunk (8 nblk * 32 lanes)
#define BCH_U4 (NK16 * CHUNK_U4)      // 5632 uint4 per channel

__device__ float g_P[(size_t)4 * IC * PCH];
__device__ uint4 g_W[(size_t)IC * BCH_U4];     // B tf32 frags: [c][q][nblk][lane] = {k0,k4,k8,k12}
__device__ float g_ss[OC];
__device__ float g_scale[OC];

// ---------------- helpers ----------------
static __device__ __forceinline__ uint32_t to_tf32(float x) {
    uint32_t r; asm("cvt.rn.tf32.f32 %0, %1;" : "=r"(r) : "f"(x));
    return r;
}
static __device__ __forceinline__ void mma_tf32(float* d, const uint32_t* a,
                                                uint32_t b0, uint32_t b1) {
    asm volatile("mma.sync.aligned.m16n8k8.row.col.f32.tf32.tf32.f32 "
        "{%0,%1,%2,%3}, {%4,%5,%6,%7}, {%8,%9}, {%0,%1,%2,%3};"
        : "+f"(d[0]), "+f"(d[1]), "+f"(d[2]), "+f"(d[3])
        : "r"(a[0]), "r"(a[1]), "r"(a[2]), "r"(a[3]), "r"(b0), "r"(b1));
}

#define CPA(dst, src) asm volatile("cp.async.cg.shared.global [%0], [%1], 16;" :: "r"(dst), "l"(src))
#define CPC() asm volatile("cp.async.commit_group;" ::)
#define CPW1() asm volatile("cp.async.wait_group 1;" ::: "memory")
#define CPW0() asm volatile("cp.async.wait_group 0;" ::: "memory")

// ---------------- K1: build weights into tf32 mma B-fragment layout ----------------
__global__ void build_w_kernel(
    int c0, int c1,
    const float* __restrict__ wss, const float* __restrict__ wsv, const float* __restrict__ wst,
    const float* __restrict__ wvs, const float* __restrict__ wvv, const float* __restrict__ wvt,
    const float* __restrict__ bss, const float* __restrict__ bsv, const float* __restrict__ bst,
    const float* __restrict__ bvs, const float* __restrict__ bvv, const float* __restrict__ bvt) {
    int idx = blockIdx.x * blockDim.x + threadIdx.x;
    int n = (c1 - c0) * KTAPS * 64;
    if (idx >= n) return;
    int oc  = idx & 63;
    int tap = (idx >> 6) % KTAPS;
    int c   = c0 + idx / (KTAPS * 64);

    float val = 0.f;
    if (tap < 343) {
        int u, io, dout;
        if (oc < 16) { u = oc; io = 0; dout = 1; }
        else         { u = (oc - 16) / 3; io = (oc - 16) % 3; dout = 3; }
        int v, ji, din;
        if (c < 16)       { v = c;            ji = 0;            din = 1; }
        else if (c < 64)  { v = (c - 16) / 3; ji = (c - 16) % 3; din = 3; }
        else              { v = (c - 64) / 9; ji = (c - 64) % 9; din = 9; }
        const float* w; const float* bs; int nb;
        if (oc < 16) {
            if (c < 16)      { w = wss; bs = bss; nb = 3; }
            else if (c < 64) { w = wsv; bs = bsv; nb = 3; }
            else             { w = wst; bs = bst; nb = 9; }
        } else {
            if (c < 16)      { w = wvs; bs = bvs; nb = 3; }
            else if (c < 64) { w = wvv; bs = bvv; nb = 9; }
            else             { w = wvt; bs = bvt; nb = 21; }
        }
        for (int bb = 0; bb < nb; bb++)
            val = fmaf(w[(u * 16 + v) * nb + bb],
                       bs[((bb * dout + io) * din + ji) * 343 + tap], val);
    }
    // B fragment (m16n8k8 row.col): lane = (oc%8)*4 + (kk%4); word = kk/4
    int q = tap >> 4, kk = tap & 15;
    int j = oc >> 3;
    int lane = ((oc & 7) << 2) + (kk & 3);
    size_t u4 = ((size_t)c * NK16 + q) * CHUNK_U4 + j * 32 + lane;
    ((uint32_t*)&g_W[u4])[kk >> 2] = to_tf32(val);
}

// ---------------- K2: padded svt ----------------
__global__ void pad_kernel(const float* __restrict__ sv) {
    long long idx = (long long)blockIdx.x * 256 + threadIdx.x;
    if (idx >= (long long)4 * IC * PCH) return;
    int bc = (int)(idx / PCH);
    int r  = (int)(idx - (long long)bc * PCH);
    int b = bc / IC, c = bc % IC;
    int pd = r / (PH * PW); r -= pd * (PH * PW);
    int ph = r / PW;
    int pw = r - ph * PW;
    int id = pd - 3, ih = ph - 3, iw = pw - 3;
    float val = 0.f;
    if ((unsigned)id < 32u && (unsigned)ih < 32u && (unsigned)iw < 32u) {
        int off = id * 1024 + ih * 32 + iw;
        const float* svb = sv + (size_t)b * 64 * 32768;
        if (c < 64) val = svb[(size_t)c * 32768 + off];
        else {
            int cc = c - 64, u = cc / 9, comp = cc % 9;
            val = svb[(size_t)(16 + u * 3 + comp / 3) * 32768 + off] *
                  svb[(size_t)(16 + u * 3 + comp % 3) * 32768 + off];
        }
    }
    g_P[idx] = val;
}

// ---------------- K3: mma.sync tf32 implicit-GEMM conv (R7 structure) ----------------
// 256 thr = 8 warps; warp w: 16 voxels (w*16 + lane/4, +8) x 64 oc.
extern __shared__ float smem[];

__global__ void __launch_bounds__(256, 1)
conv_kernel(float* __restrict__ out) {
    int*   tapoff = (int*)smem;
    float* s_in   = smem + 352;
    uint4* s_B    = (uint4*)(smem + 352 + 2 * 4536);

    const int tid = threadIdx.x, lane = tid & 31, w = tid >> 5;
    const int tile = blockIdx.x, b = blockIdx.y;
    const int td = (tile >> 2) * 2, th = ((tile >> 1) & 1) * 8, tw = (tile & 1) * 8;

    for (int t = tid; t < KTAPS; t += 256) {
        int kd = t / 49, r = t % 49, kh = r / 7, kw = r % 7;
        tapoff[t] = (t < 343) ? (kd * 504 + kh * 24 + kw) : 0;
    }

    const int c4 = lane & 3;
    const int m0 = w * 16 + (lane >> 2), m1 = m0 + 8;
    const int g0 = (m0 >> 6) * 1008 + ((m0 >> 3) & 7) * 48 + (m0 & 7) * 2;
    const int g1 = (m1 >> 6) * 1008 + ((m1 >> 3) & 7) * 48 + (m1 & 7) * 2;

    const uint32_t inb = (uint32_t)__cvta_generic_to_shared(s_in);
    const uint32_t Bb  = (uint32_t)__cvta_generic_to_shared(s_B);

    auto stage = [&](int c) {
        int buf = c & 1;
        const float* src = g_P + ((size_t)b * IC + c) * PCH
                         + (2 * td) * (PH * PW) + (2 * th) * PW + (2 * tw);
        uint32_t dsti = inb + (uint32_t)buf * 4536 * 4;
        for (int i = tid; i < 189 * 6; i += 256) {
            int dd = i / 126, r2 = i - dd * 126, dh = r2 / 6, ch = r2 - dh * 6;
            CPA(dsti + ((dd * 21 + dh) * 24 + ch * 4) * 4,
                src + dd * (PH * PW) + dh * PW + ch * 4);
        }
        const uint4* bsrc = g_W + (size_t)c * BCH_U4;
        uint32_t dstb = Bb + (uint32_t)buf * BCH_U4 * 16;
        for (int i = tid; i < BCH_U4; i += 256) CPA(dstb + i * 16, bsrc + i);
    };

    float acc[8][4];
#pragma unroll
    for (int j = 0; j < 8; j++)
#pragma unroll
        for (int k = 0; k < 4; k++) acc[j][k] = 0.f;

    stage(0); CPC();
    stage(1); CPC();

    for (int c = 0; c < IC; c++) {
        if (c < IC - 1) CPW1(); else CPW0();
        __syncthreads();

        const float* si = s_in + (c & 1) * 4536;
        const uint4* Bc = s_B + (c & 1) * BCH_U4;

#pragma unroll 1
        for (int q = 0; q < NK16; q++) {
            const int* tq = tapoff + q * 16 + c4;
            int o0 = tq[0], o1 = tq[4], o2 = tq[8], o3 = tq[12];

            // A fragments: rows m0/m1, ks = c4, c4+4 (mma#1) and c4+8, c4+12 (mma#2)
            uint32_t a1[4], a2[4];
            a1[0] = to_tf32(si[g0 + o0]); a1[1] = to_tf32(si[g1 + o0]);
            a1[2] = to_tf32(si[g0 + o1]); a1[3] = to_tf32(si[g1 + o1]);
            a2[0] = to_tf32(si[g0 + o2]); a2[1] = to_tf32(si[g1 + o2]);
            a2[2] = to_tf32(si[g0 + o3]); a2[3] = to_tf32(si[g1 + o3]);

            const uint4* Bq = Bc + q * CHUNK_U4 + lane;
#pragma unroll
            for (int j = 0; j < 8; j++) {
                uint4 bb = Bq[j * 32];
                mma_tf32(acc[j], a1, bb.x, bb.y);   // k 0..7
                mma_tf32(acc[j], a2, bb.z, bb.w);   // k 8..15
            }
        }

        if (c + 2 < IC) {
            __syncthreads();
            stage(c + 2); CPC();
        }
    }

    // epilogue: D frag (row lane/4 [+8], col j*8 + 2*c4 [+1])
    const int od0 = td + (m0 >> 6), oh0 = th + ((m0 >> 3) & 7), ow0 = tw + (m0 & 7);
    const int od1 = td + (m1 >> 6), oh1 = th + ((m1 >> 3) & 7), ow1 = tw + (m1 & 7);
    float* ob = out + (size_t)b * OC * 4096;
    const int v0 = od0 * 256 + oh0 * 16 + ow0;
    const int v1 = od1 * 256 + oh1 * 16 + ow1;
#pragma unroll
    for (int j = 0; j < 8; j++) {
        int oc0 = j * 8 + 2 * c4;
        ob[(size_t)oc0 * 4096 + v0]       = acc[j][0];
        ob[(size_t)(oc0 + 1) * 4096 + v0] = acc[j][1];
        ob[(size_t)oc0 * 4096 + v1]       = acc[j][2];
        ob[(size_t)(oc0 + 1) * 4096 + v1] = acc[j][3];
    }
}

// ---------------- epilogue kernels ----------------
__global__ void sumsq_kernel(const float* __restrict__ y) {
    __shared__ float red[256];
    const int ch = blockIdx.x, tid = threadIdx.x;
    float s = 0.f;
    for (int i = tid; i < 4 * 4096; i += 256) {
        int b = i >> 12, sp = i & 4095;
        float v = y[((size_t)b * OC + ch) * 4096 + sp];
        s = fmaf(v, v, s);
    }
    red[tid] = s;
    __syncthreads();
    for (int o = 128; o > 0; o >>= 1) {
        if (tid < o) red[tid] += red[tid + o];
        __syncthreads();
    }
    if (tid == 0) g_ss[ch] = red[0];
}

__global__ void finalize_kernel(const float* __restrict__ bngs, const float* __restrict__ bngv) {
    int ch = threadIdx.x;
    float sc;
    if (ch < 16) sc = bngs[ch] / sqrtf(g_ss[ch] / 16384.f + EPSV);
    else {
        int u = (ch - 16) / 3;
        sc = bngv[u] / sqrtf((g_ss[16 + 3 * u] + g_ss[17 + 3 * u] + g_ss[18 + 3 * u]) / 49152.f + EPSV);
    }
    g_scale[ch] = sc;
}

__global__ void scale_act_kernel(float* __restrict__ y, const float* __restrict__ bias) {
    int i = blockIdx.x * 256 + threadIdx.x;
    int ch = (i >> 12) & 63;
    float v = y[i] * g_scale[ch];
    if (ch < 16) v = fmaxf(v + bias[ch], 0.f);
    y[i] = v;
}

// ---------------- launch ----------------
extern "C" void kernel_launch(void* const* d_in, const int* in_sizes, int n_in,
                              void* d_out, int out_size) {
    const float* sv = (const float*)d_in[0];
    const float *wss, *wsv, *wst, *wvs, *wvv, *wvt;
    const float *bss, *bsv, *bst, *bvs, *bvv, *bvt;
    if (in_sizes[1] == 1029) {
        bss = (const float*)d_in[1];  wss = (const float*)d_in[2];
        bsv = (const float*)d_in[3];  wsv = (const float*)d_in[4];
        bst = (const float*)d_in[5];  wst = (const float*)d_in[6];
        bvs = (const float*)d_in[7];  wvs = (const float*)d_in[8];
        bvv = (const float*)d_in[9];  wvv = (const float*)d_in[10];
        bvt = (const float*)d_in[11]; wvt = (const float*)d_in[12];
    } else {
        wss = (const float*)d_in[1];  wsv = (const float*)d_in[2];  wst = (const float*)d_in[3];
        wvs = (const float*)d_in[4];  wvv = (const float*)d_in[5];  wvt = (const float*)d_in[6];
        bss = (const float*)d_in[7];  bsv = (const float*)d_in[8];  bst = (const float*)d_in[9];
        bvs = (const float*)d_in[10]; bvv = (const float*)d_in[11]; bvt = (const float*)d_in[12];
    }
    const float* bngs = (const float*)d_in[13];
    const float* bngv = (const float*)d_in[14];
    const float* bias = (const float*)d_in[15];
    float* out = (float*)d_out;

    const int SMEM_BYTES = (352 + 2 * 4536 + 2 * BCH_U4 * 4) * 4;   // 217,920 B
    cudaFuncSetAttribute(conv_kernel, cudaFuncAttributeMaxDynamicSharedMemorySize, SMEM_BYTES);

    int n1 = 104 * KTAPS * 64;
    build_w_kernel<<<(n1 + 255) / 256, 256>>>(0, 104, wss, wsv, wst, wvs, wvv, wvt,
                                              bss, bsv, bst, bvs, bvv, bvt);
    build_w_kernel<<<(n1 + 255) / 256, 256>>>(104, 208, wss, wsv, wst, wvs, wvv, wvt,
                                              bss, bsv, bst, bvs, bvv, bvt);
    long long nP = (long long)4 * IC * PCH;
    pad_kernel<<<(unsigned)((nP + 255) / 256), 256>>>(sv);
    conv_kernel<<<dim3(32, 4), 256, SMEM_BYTES>>>(out);
    sumsq_kernel<<<64, 256>>>(out);
    finalize_kernel<<<1, 64>>>(bngs, bngv);
    scale_act_kernel<<<4096, 256>>>(out, bias);
}